// round 12
// baseline (speedup 1.0000x reference)
#include <cuda_runtime.h>

// BurstSnn: burst encoder + 2-layer LIF SNN, 32 timesteps.
// x [B,187] f32, W1 [50,187] f32, W2 [5,50] f32
// out: spk_rec [32,B,5] f32 then counts [B] f32
//
// Encoder = 8-entry LUT on floor(8x) (exact); all input spikes end by t=5.
// Two samples/warp (16-lane halves). t0/t1 complement accumulation vs W1
// column sums; t2..t5 sparse events. DUAL accumulator chains in the event
// loop (even->A, odd->B, merged per step) to halve FADD dependency length.
// spk_rec pre-zeroed by cudaMemsetAsync; kernel stores only 1.0s.

#define T_STEPS 32
#define DDIM 187
#define HDIM 50
#define CDIM 5
#define NGRP 12
#define W1PAD 52          // floats per W1 row (208 B, 16B-aligned)
#define W1TAIL 16
#define W2PAD 68          // 272 B rows

// per-bucket spike-time masks, packed byte k = pattern(bucket k)
#define PAT_PACK 0x071B2B0B03050100ull

__device__ __forceinline__ void addx2(unsigned long long &a, unsigned long long b) {
    asm("add.rn.f32x2 %0, %1, %2;" : "=l"(a) : "l"(a), "l"(b));
}
__device__ __forceinline__ void mulx2(unsigned long long &a, unsigned long long b) {
    asm("mul.rn.f32x2 %0, %1, %2;" : "=l"(a) : "l"(a), "l"(b));
}
__device__ __forceinline__ unsigned long long packx2(float lo, float hi) {
    unsigned long long r; asm("mov.b64 %0, {%1,%2};" : "=l"(r) : "f"(lo), "f"(hi)); return r;
}
__device__ __forceinline__ void unpackx2(unsigned long long v, float &lo, float &hi) {
    asm("mov.b64 {%0,%1}, %2;" : "=f"(lo), "=f"(hi) : "l"(v));
}

// pair-unrolled event accumulation, DUAL chains: even events -> A, odd -> B
__device__ __forceinline__ void ev_accum2(unsigned mh, const char* gb,
                                          unsigned long long &A01,
                                          unsigned long long &A23,
                                          unsigned long long &B01,
                                          unsigned long long &B23) {
    while (mh) {
        int i0 = __ffs(mh) - 1; mh &= mh - 1;
        const ulonglong2 w0 = *(const ulonglong2*)(gb + i0 * 208);
        if (mh) {
            int i1 = __ffs(mh) - 1; mh &= mh - 1;
            const ulonglong2 w1 = *(const ulonglong2*)(gb + i1 * 208);
            addx2(A01, w0.x); addx2(A23, w0.y);
            addx2(B01, w1.x); addx2(B23, w1.y);
        } else {
            addx2(A01, w0.x); addx2(A23, w0.y);
        }
    }
}

// layer-2 sparse gather + LIF2 + store; returns (anyS1|anyS2)
__device__ __forceinline__ unsigned step_tail(bool s0, bool s1, bool s2, bool s3,
                                              int hl, int shamt,
                                              const float* __restrict__ w2b,
                                              float &m2, bool valid,
                                              float* &po, size_t tstride4) {
    unsigned b0 = __ballot_sync(0xffffffffu, s0);
    unsigned b1 = __ballot_sync(0xffffffffu, s1);
    unsigned b2 = __ballot_sync(0xffffffffu, s2);
    unsigned b3 = __ballot_sync(0xffffffffu, s3);
    unsigned anyS1 = b0 | b1 | b2 | b3;
    float cur2 = 0.0f;
    if (anyS1) {
        unsigned f;
        f = (b0 >> shamt) & 0xffffu;
        while (f) { int i = __ffs(f) - 1; f &= f - 1;
                    if (hl < CDIM) cur2 += w2b[4 * i + 0]; }
        f = (b1 >> shamt) & 0xffffu;
        while (f) { int i = __ffs(f) - 1; f &= f - 1;
                    if (hl < CDIM) cur2 += w2b[4 * i + 1]; }
        f = (b2 >> shamt) & 0xffffu;
        while (f) { int i = __ffs(f) - 1; f &= f - 1;
                    if (hl < CDIM) cur2 += w2b[4 * i + 2]; }
        f = (b3 >> shamt) & 0xffffu;
        while (f) { int i = __ffs(f) - 1; f &= f - 1;
                    if (hl < CDIM) cur2 += w2b[4 * i + 3]; }
    }
    m2 = 0.9f * m2 + cur2;
    bool sp2 = (hl < CDIM) && (m2 > 1.0f);
    if (sp2) { m2 -= 1.0f; if (valid) *po = 1.0f; }
    po = (float*)((char*)po + tstride4);
    unsigned anyS2 = __ballot_sync(0xffffffffu, sp2);
    return anyS1 | anyS2;
}

__global__ __launch_bounds__(256, 5)
void burst_snn_kernel(const float* __restrict__ x,
                      const float* __restrict__ W1,
                      const float* __restrict__ W2,
                      float* __restrict__ out, int B)
{
    __shared__ __align__(16) float sW1[DDIM * W1PAD + W1TAIL];
    __shared__ float sW2[CDIM * W2PAD];
    __shared__ float sPart[4 * W1PAD];
    __shared__ __align__(16) float sCol[64];

    const int tid = threadIdx.x;
    for (int i = tid; i < DDIM * W1PAD + W1TAIL; i += 256) {
        float v = 0.0f;
        if (i < DDIM * W1PAD) {
            int d = i / W1PAD, u = i - d * W1PAD;
            if (u < HDIM) v = W1[u * DDIM + d];
        }
        sW1[i] = v;
    }
    for (int i = tid; i < CDIM * W2PAD; i += 256) {
        int c = i / W2PAD, h = i - c * W2PAD;
        sW2[i] = (h < HDIM) ? W2[c * HDIM + h] : 0.0f;
    }
    __syncthreads();

    // ---- column sums of sW1 ----
    if (tid < 4 * W1PAD) {
        int u = tid % W1PAD, seg = tid / W1PAD;
        float sa = 0.0f, sb = 0.0f;
        int d = seg;
        for (; d + 4 < DDIM; d += 8) {
            sa += sW1[d * W1PAD + u];
            sb += sW1[(d + 4) * W1PAD + u];
        }
        for (; d < DDIM; d += 4) sa += sW1[d * W1PAD + u];
        sPart[seg * W1PAD + u] = sa + sb;
    }
    __syncthreads();
    if (tid < 64) {
        float v = 0.0f;
        if (tid < W1PAD)
            v = sPart[tid] + sPart[W1PAD + tid] + sPart[2 * W1PAD + tid]
              + sPart[3 * W1PAD + tid];
        sCol[tid] = v;
    }
    __syncthreads();

    const int lane = tid & 31;
    const int hl   = lane & 15;
    const int half = lane >> 4;
    const int b    = (blockIdx.x * 8 + (tid >> 5)) * 2 + half;
    const bool valid = (b < B);

    const unsigned long long BETA2 = packx2(0.9f, 0.9f);

    // ---- encoder LUT: spike pattern per dim (d = hl + 16*j) ----
    unsigned pat[NGRP];
    int cnt = 0;
    const float* xb = x + (size_t)b * DDIM;
#pragma unroll
    for (int j = 0; j < NGRP; j++) {
        int d = hl + 16 * j;
        unsigned p = 0u;
        if (valid && d < DDIM) {
            unsigned bucket = (unsigned)(xb[d] * 8.0f);     // exact: x in [0,1)
            p = (unsigned)((PAT_PACK >> (bucket * 8)) & 0xffu);
        }
        pat[j] = p;
        cnt += __popc(p);
    }

    const bool v01 = (hl < 13), v23 = (hl < 12);

    unsigned long long m01, m23;                 // mem1 packed pairs
    float m2 = 0.0f;

    const char*  wb  = (const char*)sW1 + hl * 16;
    const float* w2b = sW2 + hl * W2PAD;
    const int shamt = lane & 16;
    float* po = out + (size_t)b * CDIM + hl;
    const size_t tstride4 = (size_t)B * CDIM * sizeof(float);

    const ulonglong2 cs = *(const ulonglong2*)((const char*)sCol + hl * 16);
    float g0, g1, g2, g3;
    unpackx2(cs.x, g0, g1); unpackx2(cs.y, g2, g3);

    // ================= t = 0 (complement; 87.5% spike) =================
    {
        unsigned long long c01 = 0ull, c23 = 0ull, d01 = 0ull, d23 = 0ull;
#pragma unroll
        for (int j = 0; j < NGRP; j++) {
            unsigned bal = __ballot_sync(0xffffffffu, (pat[j] & 1u) != 0u);
            unsigned mh = ((~bal) >> shamt) & ((j == NGRP - 1) ? 0x07ffu : 0xffffu);
            ev_accum2(mh, wb + j * (16 * 208), c01, c23, d01, d23);
        }
        addx2(c01, d01); addx2(c23, d23);
        float c0, c1, c2, c3;
        unpackx2(c01, c0, c1); unpackx2(c23, c2, c3);
        float a0 = g0 - c0, a1 = g1 - c1, a2 = g2 - c2, a3 = g3 - c3;
        bool s0 = v01 && (a0 > 1.0f), s1 = v01 && (a1 > 1.0f);
        bool s2 = v23 && (a2 > 1.0f), s3 = v23 && (a3 > 1.0f);
        if (s0) a0 -= 1.0f; if (s1) a1 -= 1.0f;
        if (s2) a2 -= 1.0f; if (s3) a3 -= 1.0f;
        m01 = packx2(a0, a1); m23 = packx2(a2, a3);
        step_tail(s0, s1, s2, s3, hl, shamt, w2b, m2, valid, po, tstride4);
    }

    // ================= t = 1 (complement; 62.5% spike) =================
    {
        mulx2(m01, BETA2); mulx2(m23, BETA2);
        unsigned long long c01 = 0ull, c23 = 0ull, d01 = 0ull, d23 = 0ull;
#pragma unroll
        for (int j = 0; j < NGRP; j++) {
            unsigned bal = __ballot_sync(0xffffffffu, (pat[j] & 2u) != 0u);
            unsigned mh = ((~bal) >> shamt) & ((j == NGRP - 1) ? 0x07ffu : 0xffffu);
            ev_accum2(mh, wb + j * (16 * 208), c01, c23, d01, d23);
        }
        addx2(c01, d01); addx2(c23, d23);
        float a0, a1, a2, a3, c0, c1, c2, c3;
        unpackx2(m01, a0, a1); unpackx2(m23, a2, a3);
        unpackx2(c01, c0, c1); unpackx2(c23, c2, c3);
        a0 += g0 - c0; a1 += g1 - c1; a2 += g2 - c2; a3 += g3 - c3;
        bool s0 = v01 && (a0 > 1.0f), s1 = v01 && (a1 > 1.0f);
        bool s2 = v23 && (a2 > 1.0f), s3 = v23 && (a3 > 1.0f);
        if (s0) a0 -= 1.0f; if (s1) a1 -= 1.0f;
        if (s2) a2 -= 1.0f; if (s3) a3 -= 1.0f;
        m01 = packx2(a0, a1); m23 = packx2(a2, a3);
        step_tail(s0, s1, s2, s3, hl, shamt, w2b, m2, valid, po, tstride4);
    }

    // ============ t = 2..5 (sparse; 25/37.5/12.5/12.5% spike) ============
#pragma unroll
    for (int t = 2; t < 6; t++) {
        mulx2(m01, BETA2); mulx2(m23, BETA2);
        unsigned long long z01 = 0ull, z23 = 0ull;   // second chain this step
        const unsigned bit = 1u << t;
#pragma unroll
        for (int j = 0; j < NGRP; j++) {
            unsigned bal = __ballot_sync(0xffffffffu, (pat[j] & bit) != 0u);
            if (bal) {
                unsigned mh = (bal >> shamt) & 0xffffu;
                ev_accum2(mh, wb + j * (16 * 208), m01, m23, z01, z23);
            }
        }
        addx2(m01, z01); addx2(m23, z23);
        float a0, a1, a2, a3;
        unpackx2(m01, a0, a1); unpackx2(m23, a2, a3);
        bool s0 = v01 && (a0 > 1.0f), s1 = v01 && (a1 > 1.0f);
        bool s2 = v23 && (a2 > 1.0f), s3 = v23 && (a3 > 1.0f);
        if (s0) a0 -= 1.0f; if (s1) a1 -= 1.0f;
        if (s2) a2 -= 1.0f; if (s3) a3 -= 1.0f;
        m01 = packx2(a0, a1); m23 = packx2(a2, a3);
        step_tail(s0, s1, s2, s3, hl, shamt, w2b, m2, valid, po, tstride4);
    }

    // ============ tail t >= 6: encoder silent, LIF decay only ============
#pragma unroll 1
    for (int t = 6; t < T_STEPS; t++) {
        mulx2(m01, BETA2); mulx2(m23, BETA2);
        float a0, a1, a2, a3;
        unpackx2(m01, a0, a1); unpackx2(m23, a2, a3);
        bool s0 = v01 && (a0 > 1.0f), s1 = v01 && (a1 > 1.0f);
        bool s2 = v23 && (a2 > 1.0f), s3 = v23 && (a3 > 1.0f);
        if (s0) a0 -= 1.0f; if (s1) a1 -= 1.0f;
        if (s2) a2 -= 1.0f; if (s3) a3 -= 1.0f;
        m01 = packx2(a0, a1); m23 = packx2(a2, a3);
        unsigned any = step_tail(s0, s1, s2, s3, hl, shamt, w2b, m2,
                                 valid, po, tstride4);
        if (any == 0u) break;    // membranes <= 1, only decay: all zero ahead
    }

    // ---- spike counts (closed form; reduce within 16-lane half) ----
#pragma unroll
    for (int off = 8; off; off >>= 1)
        cnt += __shfl_xor_sync(0xffffffffu, cnt, off);
    if (valid && hl == 0)
        out[(size_t)T_STEPS * B * CDIM + b] = (float)cnt;
}

extern "C" void kernel_launch(void* const* d_in, const int* in_sizes, int n_in,
                              void* d_out, int out_size)
{
    const float* x  = (const float*)d_in[0];
    const float* W1 = (const float*)d_in[1];
    const float* W2 = (const float*)d_in[2];
    float* out = (float*)d_out;

    int B = in_sizes[0] / DDIM;
    // pre-zero spk_rec [32,B,5]; counts written by kernel
    cudaMemsetAsync(out, 0, (size_t)T_STEPS * B * CDIM * sizeof(float));
    int blocks = (B + 15) / 16;   // 8 warps/block, 2 samples/warp
    burst_snn_kernel<<<blocks, 256>>>(x, W1, W2, out, B);
}

// round 13
// speedup vs baseline: 1.1272x; 1.1272x over previous
#include <cuda_runtime.h>

// BurstSnn: burst encoder + 2-layer LIF SNN, 32 timesteps.
// x [B,187] f32, W1 [50,187] f32, W2 [5,50] f32
// out: spk_rec [32,B,5] f32 then counts [B] f32
//
// Encoder = 8-entry LUT on floor(8x); spikes end by t=5. Two samples/warp.
// NO shared memory: transposed W1 / colsums / padded W2 live in __device__
// globals (prep kernel), cached once per SM in L1 and shared by all resident
// blocks -> 7 blocks/SM, grid 1024 fits in ONE wave (was 2 waves at 5/SM).
// Patterns packed 12x8b into 3 regs; __reduce_or_sync unions skip dead
// groups in t2..t5 without ballots. spk_rec pre-zeroed by cudaMemsetAsync.

#define T_STEPS 32
#define DDIM 187
#define HDIM 50
#define CDIM 5
#define NGRP 12
#define W1PAD 52          // floats per W1t row (208 B, 16B-aligned)
#define W2PAD 68

// per-bucket spike-time masks, packed byte k = pattern(bucket k)
#define PAT_PACK 0x071B2B0B03050100ull

__device__ __align__(16) float g_w1t[DDIM * W1PAD + 16];  // [d][u] transposed
__device__ __align__(16) float g_col[64];                 // column sums
__device__ __align__(16) float g_w2[16 * W2PAD];          // padded W2 rows

__device__ __forceinline__ void addx2(unsigned long long &a, unsigned long long b) {
    asm("add.rn.f32x2 %0, %1, %2;" : "=l"(a) : "l"(a), "l"(b));
}
__device__ __forceinline__ void mulx2(unsigned long long &a, unsigned long long b) {
    asm("mul.rn.f32x2 %0, %1, %2;" : "=l"(a) : "l"(a), "l"(b));
}
__device__ __forceinline__ unsigned long long packx2(float lo, float hi) {
    unsigned long long r; asm("mov.b64 %0, {%1,%2};" : "=l"(r) : "f"(lo), "f"(hi)); return r;
}
__device__ __forceinline__ void unpackx2(unsigned long long v, float &lo, float &hi) {
    asm("mov.b64 {%0,%1}, %2;" : "=f"(lo), "=f"(hi) : "l"(v));
}

// ---------------- prep: transpose W1, colsums, pad W2 ----------------
__global__ void prep_kernel(const float* __restrict__ W1,
                            const float* __restrict__ W2)
{
    const int tid = threadIdx.x;
    const int blk = blockIdx.x;
    if (blk < 38) {                       // transpose 187x50 -> [d][52]
        int idx = blk * 256 + tid;
        if (idx < DDIM * W1PAD) {
            int d = idx / W1PAD, u = idx - d * W1PAD;
            g_w1t[idx] = (u < HDIM) ? W1[u * DDIM + d] : 0.0f;
        }
    } else if (blk == 38) {               // colsums + tails
        if (tid < 64) {
            float sa = 0.0f, sb = 0.0f;
            if (tid < HDIM) {
                const float* row = W1 + tid * DDIM;
                int d = 0;
                for (; d + 1 < DDIM; d += 2) { sa += row[d]; sb += row[d + 1]; }
                for (; d < DDIM; d++) sa += row[d];
            }
            g_col[tid] = sa + sb;
        } else if (tid < 80) {
            g_w1t[DDIM * W1PAD + (tid - 64)] = 0.0f;
        }
    } else {                              // pad W2 into 16 rows of 68
        for (int i = tid; i < 16 * W2PAD; i += 256) {
            int c = i / W2PAD, h = i - c * W2PAD;
            g_w2[i] = (c < CDIM && h < HDIM) ? W2[c * HDIM + h] : 0.0f;
        }
    }
}

// pair-unrolled single-chain event accumulation (R11 proven)
__device__ __forceinline__ void ev_accum(unsigned mh, const char* gb,
                                         unsigned long long &A01,
                                         unsigned long long &A23) {
    while (mh) {
        int i0 = __ffs(mh) - 1; mh &= mh - 1;
        const ulonglong2 w0 = *(const ulonglong2*)(gb + i0 * 208);
        if (mh) {
            int i1 = __ffs(mh) - 1; mh &= mh - 1;
            const ulonglong2 w1 = *(const ulonglong2*)(gb + i1 * 208);
            addx2(A01, w0.x); addx2(A23, w0.y);
            addx2(A01, w1.x); addx2(A23, w1.y);
        } else {
            addx2(A01, w0.x); addx2(A23, w0.y);
        }
    }
}

// layer-2 sparse gather + LIF2 + store; returns (anyS1|anyS2)
__device__ __forceinline__ unsigned step_tail(bool s0, bool s1, bool s2, bool s3,
                                              int hl, int shamt,
                                              const float* __restrict__ w2b,
                                              float &m2, bool valid,
                                              float* &po, unsigned tstride4) {
    unsigned b0 = __ballot_sync(0xffffffffu, s0);
    unsigned b1 = __ballot_sync(0xffffffffu, s1);
    unsigned b2 = __ballot_sync(0xffffffffu, s2);
    unsigned b3 = __ballot_sync(0xffffffffu, s3);
    unsigned anyS1 = b0 | b1 | b2 | b3;
    float cur2 = 0.0f;
    if (anyS1) {
        unsigned f;
        f = (b0 >> shamt) & 0xffffu;
        while (f) { int i = __ffs(f) - 1; f &= f - 1;
                    if (hl < CDIM) cur2 += w2b[4 * i + 0]; }
        f = (b1 >> shamt) & 0xffffu;
        while (f) { int i = __ffs(f) - 1; f &= f - 1;
                    if (hl < CDIM) cur2 += w2b[4 * i + 1]; }
        f = (b2 >> shamt) & 0xffffu;
        while (f) { int i = __ffs(f) - 1; f &= f - 1;
                    if (hl < CDIM) cur2 += w2b[4 * i + 2]; }
        f = (b3 >> shamt) & 0xffffu;
        while (f) { int i = __ffs(f) - 1; f &= f - 1;
                    if (hl < CDIM) cur2 += w2b[4 * i + 3]; }
    }
    m2 = 0.9f * m2 + cur2;
    bool sp2 = (hl < CDIM) && (m2 > 1.0f);
    if (sp2) { m2 -= 1.0f; if (valid) *po = 1.0f; }
    po = (float*)((char*)po + tstride4);
    unsigned anyS2 = __ballot_sync(0xffffffffu, sp2);
    return anyS1 | anyS2;
}

// pattern bit of group j at time t from packed words (j,t compile-time)
#define PATW(j)  ((j) < 4 ? pA : ((j) < 8 ? pB : pC))
#define UNIW(j)  ((j) < 4 ? uA : ((j) < 8 ? uB : uC))
#define PBIT(j,t) ((PATW(j) >> (8 * ((j) & 3) + (t))) & 1u)
#define UBIT(j,t) ((UNIW(j) >> (8 * ((j) & 3) + (t))) & 1u)

__global__ __launch_bounds__(256, 7)
void burst_snn_kernel(const float* __restrict__ x,
                      float* __restrict__ out, int B)
{
    const int tid  = threadIdx.x;
    const int lane = tid & 31;
    const int hl   = lane & 15;
    const int half = lane >> 4;
    const int b    = (blockIdx.x * 8 + (tid >> 5)) * 2 + half;
    const bool valid = (b < B);

    const unsigned long long BETA2 = packx2(0.9f, 0.9f);

    // ---- encoder LUT: packed spike patterns, byte per group ----
    const float* xb = x + (size_t)b * DDIM;
    unsigned pA = 0u, pB = 0u, pC = 0u;
#pragma unroll
    for (int j = 0; j < NGRP; j++) {
        int d = hl + 16 * j;
        unsigned p = 0u;
        if (valid && d < DDIM) {
            unsigned bucket = (unsigned)(__ldg(xb + d) * 8.0f);   // exact
            p = (unsigned)((PAT_PACK >> (bucket * 8)) & 0xffu);
        }
        if (j < 4)      pA |= p << (8 * j);
        else if (j < 8) pB |= p << (8 * (j - 4));
        else            pC |= p << (8 * (j - 8));
    }
    int cnt = __popc(pA) + __popc(pB) + __popc(pC);

    // warp-wide unions (byte-wise OR) for group skipping
    const unsigned uA = __reduce_or_sync(0xffffffffu, pA);
    const unsigned uB = __reduce_or_sync(0xffffffffu, pB);
    const unsigned uC = __reduce_or_sync(0xffffffffu, pC);

    const bool v01 = (hl < 13), v23 = (hl < 12);

    unsigned long long m01, m23;
    float m2 = 0.0f;

    const char*  wb  = (const char*)g_w1t + hl * 16;
    const float* w2b = g_w2 + hl * W2PAD;
    const int shamt = lane & 16;
    float* po = out + b * CDIM + hl;
    const unsigned tstride4 = (unsigned)B * CDIM * sizeof(float);

    const ulonglong2 cs = *(const ulonglong2*)((const char*)g_col + hl * 16);
    float g0, g1, g2, g3;
    unpackx2(cs.x, g0, g1); unpackx2(cs.y, g2, g3);

    // ================= t = 0 (complement; 87.5% spike) =================
    {
        unsigned long long c01 = 0ull, c23 = 0ull;
#pragma unroll
        for (int j = 0; j < NGRP; j++) {
            unsigned bal = __ballot_sync(0xffffffffu, PBIT(j, 0) != 0u);
            unsigned mh = ((~bal) >> shamt) & ((j == NGRP - 1) ? 0x07ffu : 0xffffu);
            ev_accum(mh, wb + j * (16 * 208), c01, c23);
        }
        float c0, c1, c2, c3;
        unpackx2(c01, c0, c1); unpackx2(c23, c2, c3);
        float a0 = g0 - c0, a1 = g1 - c1, a2 = g2 - c2, a3 = g3 - c3;
        bool s0 = v01 && (a0 > 1.0f), s1 = v01 && (a1 > 1.0f);
        bool s2 = v23 && (a2 > 1.0f), s3 = v23 && (a3 > 1.0f);
        if (s0) a0 -= 1.0f; if (s1) a1 -= 1.0f;
        if (s2) a2 -= 1.0f; if (s3) a3 -= 1.0f;
        m01 = packx2(a0, a1); m23 = packx2(a2, a3);
        step_tail(s0, s1, s2, s3, hl, shamt, w2b, m2, valid, po, tstride4);
    }

    // ================= t = 1 (complement; 62.5% spike) =================
    {
        mulx2(m01, BETA2); mulx2(m23, BETA2);
        unsigned long long c01 = 0ull, c23 = 0ull;
#pragma unroll
        for (int j = 0; j < NGRP; j++) {
            unsigned bal = __ballot_sync(0xffffffffu, PBIT(j, 1) != 0u);
            unsigned mh = ((~bal) >> shamt) & ((j == NGRP - 1) ? 0x07ffu : 0xffffu);
            ev_accum(mh, wb + j * (16 * 208), c01, c23);
        }
        float a0, a1, a2, a3, c0, c1, c2, c3;
        unpackx2(m01, a0, a1); unpackx2(m23, a2, a3);
        unpackx2(c01, c0, c1); unpackx2(c23, c2, c3);
        a0 += g0 - c0; a1 += g1 - c1; a2 += g2 - c2; a3 += g3 - c3;
        bool s0 = v01 && (a0 > 1.0f), s1 = v01 && (a1 > 1.0f);
        bool s2 = v23 && (a2 > 1.0f), s3 = v23 && (a3 > 1.0f);
        if (s0) a0 -= 1.0f; if (s1) a1 -= 1.0f;
        if (s2) a2 -= 1.0f; if (s3) a3 -= 1.0f;
        m01 = packx2(a0, a1); m23 = packx2(a2, a3);
        step_tail(s0, s1, s2, s3, hl, shamt, w2b, m2, valid, po, tstride4);
    }

    // ===== t = 2..5 (sparse; union-skip dead groups without ballots) =====
#pragma unroll
    for (int t = 2; t < 6; t++) {
        mulx2(m01, BETA2); mulx2(m23, BETA2);
#pragma unroll
        for (int j = 0; j < NGRP; j++) {
            if (!UBIT(j, t)) continue;               // warp-uniform skip
            unsigned bal = __ballot_sync(0xffffffffu, PBIT(j, t) != 0u);
            unsigned mh = (bal >> shamt) & 0xffffu;
            ev_accum(mh, wb + j * (16 * 208), m01, m23);
        }
        float a0, a1, a2, a3;
        unpackx2(m01, a0, a1); unpackx2(m23, a2, a3);
        bool s0 = v01 && (a0 > 1.0f), s1 = v01 && (a1 > 1.0f);
        bool s2 = v23 && (a2 > 1.0f), s3 = v23 && (a3 > 1.0f);
        if (s0) a0 -= 1.0f; if (s1) a1 -= 1.0f;
        if (s2) a2 -= 1.0f; if (s3) a3 -= 1.0f;
        m01 = packx2(a0, a1); m23 = packx2(a2, a3);
        step_tail(s0, s1, s2, s3, hl, shamt, w2b, m2, valid, po, tstride4);
    }

    // ============ tail t >= 6: encoder silent, LIF decay only ============
#pragma unroll 1
    for (int t = 6; t < T_STEPS; t++) {
        mulx2(m01, BETA2); mulx2(m23, BETA2);
        float a0, a1, a2, a3;
        unpackx2(m01, a0, a1); unpackx2(m23, a2, a3);
        bool s0 = v01 && (a0 > 1.0f), s1 = v01 && (a1 > 1.0f);
        bool s2 = v23 && (a2 > 1.0f), s3 = v23 && (a3 > 1.0f);
        if (s0) a0 -= 1.0f; if (s1) a1 -= 1.0f;
        if (s2) a2 -= 1.0f; if (s3) a3 -= 1.0f;
        m01 = packx2(a0, a1); m23 = packx2(a2, a3);
        unsigned any = step_tail(s0, s1, s2, s3, hl, shamt, w2b, m2,
                                 valid, po, tstride4);
        if (any == 0u) break;    // membranes <= 1, only decay: all zero ahead
    }

    // ---- spike counts (closed form; reduce within 16-lane half) ----
#pragma unroll
    for (int off = 8; off; off >>= 1)
        cnt += __shfl_xor_sync(0xffffffffu, cnt, off);
    if (valid && hl == 0)
        out[(size_t)T_STEPS * B * CDIM + b] = (float)cnt;
}

extern "C" void kernel_launch(void* const* d_in, const int* in_sizes, int n_in,
                              void* d_out, int out_size)
{
    const float* x  = (const float*)d_in[0];
    const float* W1 = (const float*)d_in[1];
    const float* W2 = (const float*)d_in[2];
    float* out = (float*)d_out;

    int B = in_sizes[0] / DDIM;
    // pre-zero spk_rec [32,B,5]; counts written by kernel
    cudaMemsetAsync(out, 0, (size_t)T_STEPS * B * CDIM * sizeof(float));
    prep_kernel<<<40, 256>>>(W1, W2);
    int blocks = (B + 15) / 16;   // 8 warps/block, 2 samples/warp
    burst_snn_kernel<<<blocks, 256>>>(x, out, B);
}

// round 14
// speedup vs baseline: 1.2660x; 1.1232x over previous
#include <cuda_runtime.h>

// BurstSnn: burst encoder + 2-layer LIF SNN, 32 timesteps.
// x [B,187] f32, W1 [50,187] f32, W2 [5,50] f32
// out: spk_rec [32,B,5] f32 then counts [B] f32
//
// Encoder = 8-entry LUT on floor(8x); spikes end by t=5. Two samples/warp.
// No shared memory: W1t/colsums/W2 in __device__ globals (prep kernel, which
// ALSO zeroes spk_rec) -> 7 blocks/SM, grid 1024 = one wave.
// Bucket-sum reuse: t0 complement accumulator (V0) carries into t1 (only
// bucket{1,2} events added); bucket-6 sum K6 computed at t3 is reused at t4
// (t4 has NO event loop). Patterns packed 12x8b into 3 regs; union-skip.

#define T_STEPS 32
#define DDIM 187
#define HDIM 50
#define CDIM 5
#define NGRP 12
#define W1PAD 52          // floats per W1t row (208 B, 16B-aligned)
#define W2PAD 68

// per-bucket spike-time masks, packed byte k = pattern(bucket k)
#define PAT_PACK 0x071B2B0B03050100ull

__device__ __align__(16) float g_w1t[DDIM * W1PAD + 16];  // [d][u] transposed
__device__ __align__(16) float g_col[64];                 // column sums
__device__ __align__(16) float g_w2[16 * W2PAD];          // padded W2 rows

__device__ __forceinline__ void addx2(unsigned long long &a, unsigned long long b) {
    asm("add.rn.f32x2 %0, %1, %2;" : "=l"(a) : "l"(a), "l"(b));
}
__device__ __forceinline__ void mulx2(unsigned long long &a, unsigned long long b) {
    asm("mul.rn.f32x2 %0, %1, %2;" : "=l"(a) : "l"(a), "l"(b));
}
__device__ __forceinline__ unsigned long long packx2(float lo, float hi) {
    unsigned long long r; asm("mov.b64 %0, {%1,%2};" : "=l"(r) : "f"(lo), "f"(hi)); return r;
}
__device__ __forceinline__ void unpackx2(unsigned long long v, float &lo, float &hi) {
    asm("mov.b64 {%0,%1}, %2;" : "=f"(lo), "=f"(hi) : "l"(v));
}

// -------- prep: transpose W1, colsums, pad W2, zero spk_rec --------
__global__ void prep_kernel(const float* __restrict__ W1,
                            const float* __restrict__ W2,
                            float* __restrict__ out, int B)
{
    const int tid = threadIdx.x;
    const int blk = blockIdx.x;
    if (blk < 38) {                       // transpose 187x50 -> [d][52]
        int idx = blk * 256 + tid;
        if (idx < DDIM * W1PAD) {
            int d = idx / W1PAD, u = idx - d * W1PAD;
            g_w1t[idx] = (u < HDIM) ? W1[u * DDIM + d] : 0.0f;
        }
    } else if (blk == 38) {               // colsums + tails
        if (tid < 64) {
            float sa = 0.0f, sb = 0.0f;
            if (tid < HDIM) {
                const float* row = W1 + tid * DDIM;
                int d = 0;
                for (; d + 1 < DDIM; d += 2) { sa += row[d]; sb += row[d + 1]; }
                for (; d < DDIM; d++) sa += row[d];
            }
            g_col[tid] = sa + sb;
        } else if (tid < 80) {
            g_w1t[DDIM * W1PAD + (tid - 64)] = 0.0f;
        }
    } else if (blk == 39) {               // pad W2 into 16 rows of 68
        for (int i = tid; i < 16 * W2PAD; i += 256) {
            int c = i / W2PAD, h = i - c * W2PAD;
            g_w2[i] = (c < CDIM && h < HDIM) ? W2[c * HDIM + h] : 0.0f;
        }
    } else {                              // blocks 40..143: zero spk_rec
        float4* o4 = (float4*)out;
        int n4 = (T_STEPS * B * CDIM) >> 2;     // divisible by 4
        int start = (blk - 40) * 256 + tid;
        for (int i = start; i < n4; i += 104 * 256)
            o4[i] = make_float4(0.f, 0.f, 0.f, 0.f);
    }
}

// pair-unrolled single-chain event accumulation
__device__ __forceinline__ void ev_accum(unsigned mh, const char* gb,
                                         unsigned long long &A01,
                                         unsigned long long &A23) {
    while (mh) {
        int i0 = __ffs(mh) - 1; mh &= mh - 1;
        const ulonglong2 w0 = *(const ulonglong2*)(gb + i0 * 208);
        if (mh) {
            int i1 = __ffs(mh) - 1; mh &= mh - 1;
            const ulonglong2 w1 = *(const ulonglong2*)(gb + i1 * 208);
            addx2(A01, w0.x); addx2(A23, w0.y);
            addx2(A01, w1.x); addx2(A23, w1.y);
        } else {
            addx2(A01, w0.x); addx2(A23, w0.y);
        }
    }
}

// layer-2 sparse gather + LIF2 + store; returns (anyS1|anyS2)
__device__ __forceinline__ unsigned step_tail(bool s0, bool s1, bool s2, bool s3,
                                              int hl, int shamt,
                                              const float* __restrict__ w2b,
                                              float &m2, bool valid,
                                              float* &po, unsigned tstride4) {
    unsigned b0 = __ballot_sync(0xffffffffu, s0);
    unsigned b1 = __ballot_sync(0xffffffffu, s1);
    unsigned b2 = __ballot_sync(0xffffffffu, s2);
    unsigned b3 = __ballot_sync(0xffffffffu, s3);
    unsigned anyS1 = b0 | b1 | b2 | b3;
    float cur2 = 0.0f;
    if (anyS1) {
        unsigned f;
        f = (b0 >> shamt) & 0xffffu;
        while (f) { int i = __ffs(f) - 1; f &= f - 1;
                    if (hl < CDIM) cur2 += w2b[4 * i + 0]; }
        f = (b1 >> shamt) & 0xffffu;
        while (f) { int i = __ffs(f) - 1; f &= f - 1;
                    if (hl < CDIM) cur2 += w2b[4 * i + 1]; }
        f = (b2 >> shamt) & 0xffffu;
        while (f) { int i = __ffs(f) - 1; f &= f - 1;
                    if (hl < CDIM) cur2 += w2b[4 * i + 2]; }
        f = (b3 >> shamt) & 0xffffu;
        while (f) { int i = __ffs(f) - 1; f &= f - 1;
                    if (hl < CDIM) cur2 += w2b[4 * i + 3]; }
    }
    m2 = 0.9f * m2 + cur2;
    bool sp2 = (hl < CDIM) && (m2 > 1.0f);
    if (sp2) { m2 -= 1.0f; if (valid) *po = 1.0f; }
    po = (float*)((char*)po + tstride4);
    unsigned anyS2 = __ballot_sync(0xffffffffu, sp2);
    return anyS1 | anyS2;
}

// LIF1 threshold/reset + layer-2/store; returns activity flag
__device__ __forceinline__ unsigned lif_step(unsigned long long &m01,
                                             unsigned long long &m23,
                                             bool v01, bool v23,
                                             int hl, int shamt,
                                             const float* __restrict__ w2b,
                                             float &m2, bool valid,
                                             float* &po, unsigned tstride4) {
    float a0, a1, a2, a3;
    unpackx2(m01, a0, a1); unpackx2(m23, a2, a3);
    bool s0 = v01 && (a0 > 1.0f), s1 = v01 && (a1 > 1.0f);
    bool s2 = v23 && (a2 > 1.0f), s3 = v23 && (a3 > 1.0f);
    if (s0) a0 -= 1.0f; if (s1) a1 -= 1.0f;
    if (s2) a2 -= 1.0f; if (s3) a3 -= 1.0f;
    m01 = packx2(a0, a1); m23 = packx2(a2, a3);
    return step_tail(s0, s1, s2, s3, hl, shamt, w2b, m2, valid, po, tstride4);
}

// packed-pattern access (j compile-time)
#define PATW(j)   ((j) < 4 ? pA : ((j) < 8 ? pB : pC))
#define UNIW(j)   ((j) < 4 ? uA : ((j) < 8 ? uB : uC))
#define PBYTE(j)  ((PATW(j) >> (8 * ((j) & 3))) & 0xffu)
#define PBIT(j,t) ((PATW(j) >> (8 * ((j) & 3) + (t))) & 1u)
#define UBIT(j,t) ((UNIW(j) >> (8 * ((j) & 3) + (t))) & 1u)

__global__ __launch_bounds__(256, 7)
void burst_snn_kernel(const float* __restrict__ x,
                      float* __restrict__ out, int B)
{
    const int tid  = threadIdx.x;
    const int lane = tid & 31;
    const int hl   = lane & 15;
    const int half = lane >> 4;
    const int b    = (blockIdx.x * 8 + (tid >> 5)) * 2 + half;
    const bool valid = (b < B);

    const unsigned long long BETA2 = packx2(0.9f, 0.9f);

    // ---- encoder LUT: packed spike patterns, byte per group ----
    const float* xb = x + (size_t)b * DDIM;
    unsigned pA = 0u, pB = 0u, pC = 0u;
#pragma unroll
    for (int j = 0; j < NGRP; j++) {
        int d = hl + 16 * j;
        unsigned p = 0u;
        if (valid && d < DDIM) {
            unsigned bucket = (unsigned)(__ldg(xb + d) * 8.0f);   // exact
            p = (unsigned)((PAT_PACK >> (bucket * 8)) & 0xffu);
        }
        if (j < 4)      pA |= p << (8 * j);
        else if (j < 8) pB |= p << (8 * (j - 4));
        else            pC |= p << (8 * (j - 8));
    }
    int cnt = __popc(pA) + __popc(pB) + __popc(pC);

    const unsigned uA = __reduce_or_sync(0xffffffffu, pA);
    const unsigned uB = __reduce_or_sync(0xffffffffu, pB);
    const unsigned uC = __reduce_or_sync(0xffffffffu, pC);

    const bool v01 = (hl < 13), v23 = (hl < 12);

    unsigned long long m01, m23;
    float m2 = 0.0f;

    const char*  wb  = (const char*)g_w1t + hl * 16;
    const float* w2b = g_w2 + hl * W2PAD;
    const int shamt = lane & 16;
    float* po = out + b * CDIM + hl;
    const unsigned tstride4 = (unsigned)B * CDIM * sizeof(float);

    const ulonglong2 cs = *(const ulonglong2*)((const char*)g_col + hl * 16);
    float g0, g1, g2, g3;
    unpackx2(cs.x, g0, g1); unpackx2(cs.y, g2, g3);

    unsigned long long c01 = 0ull, c23 = 0ull;   // bucket-sum accumulator

    // ===== t = 0: complement (non-spikers = bucket 0) -> c = V0 =====
    {
#pragma unroll
        for (int j = 0; j < NGRP; j++) {
            unsigned bal = __ballot_sync(0xffffffffu, PBIT(j, 0) != 0u);
            unsigned mh = ((~bal) >> shamt) & ((j == NGRP - 1) ? 0x07ffu : 0xffffu);
            ev_accum(mh, wb + j * (16 * 208), c01, c23);
        }
        float c0, c1, c2, c3;
        unpackx2(c01, c0, c1); unpackx2(c23, c2, c3);
        m01 = packx2(g0 - c0, g1 - c1);
        m23 = packx2(g2 - c2, g3 - c3);
        lif_step(m01, m23, v01, v23, hl, shamt, w2b, m2, valid, po, tstride4);
    }

    // ===== t = 1: c continues (add buckets {1,2}); cur = colsum - c =====
    {
        mulx2(m01, BETA2); mulx2(m23, BETA2);
#pragma unroll
        for (int j = 0; j < NGRP; j++) {
            unsigned bal = __ballot_sync(0xffffffffu, (PBYTE(j) & 3u) == 1u);
            unsigned mh = (bal >> shamt) & 0xffffu;
            ev_accum(mh, wb + j * (16 * 208), c01, c23);
        }
        float a0, a1, a2, a3, c0, c1, c2, c3;
        unpackx2(m01, a0, a1); unpackx2(m23, a2, a3);
        unpackx2(c01, c0, c1); unpackx2(c23, c2, c3);
        a0 += g0 - c0; a1 += g1 - c1; a2 += g2 - c2; a3 += g3 - c3;
        m01 = packx2(a0, a1); m23 = packx2(a2, a3);
        lif_step(m01, m23, v01, v23, hl, shamt, w2b, m2, valid, po, tstride4);
    }

    // ===== t = 2: sparse events (buckets {2,7} = pattern bit 2) =====
    {
        mulx2(m01, BETA2); mulx2(m23, BETA2);
#pragma unroll
        for (int j = 0; j < NGRP; j++) {
            if (!UBIT(j, 2)) continue;
            unsigned bal = __ballot_sync(0xffffffffu, PBIT(j, 2) != 0u);
            unsigned mh = (bal >> shamt) & 0xffffu;
            ev_accum(mh, wb + j * (16 * 208), m01, m23);
        }
        lif_step(m01, m23, v01, v23, hl, shamt, w2b, m2, valid, po, tstride4);
    }

    // ===== t = 3: buckets {4,5} -> m ; bucket 6 -> K6 (kept for t=4) =====
    unsigned long long k01 = 0ull, k23 = 0ull;
    {
        mulx2(m01, BETA2); mulx2(m23, BETA2);
#pragma unroll
        for (int j = 0; j < NGRP; j++) {
            if (UBIT(j, 3)) {           // any of buckets {4,5,6} present
                unsigned bal = __ballot_sync(0xffffffffu,
                                             ((PBYTE(j) >> 3) & 3u) == 1u);
                unsigned mh = (bal >> shamt) & 0xffffu;
                ev_accum(mh, wb + j * (16 * 208), m01, m23);
            }
            if (UBIT(j, 4)) {           // bucket 6 present
                unsigned bal = __ballot_sync(0xffffffffu, PBIT(j, 4) != 0u);
                unsigned mh = (bal >> shamt) & 0xffffu;
                ev_accum(mh, wb + j * (16 * 208), k01, k23);
            }
        }
        addx2(m01, k01); addx2(m23, k23);
        lif_step(m01, m23, v01, v23, hl, shamt, w2b, m2, valid, po, tstride4);
    }

    // ===== t = 4: cur = K6 (no event loop) =====
    {
        mulx2(m01, BETA2); mulx2(m23, BETA2);
        addx2(m01, k01); addx2(m23, k23);
        lif_step(m01, m23, v01, v23, hl, shamt, w2b, m2, valid, po, tstride4);
    }

    // ===== t = 5: sparse events (bucket 5 = pattern bit 5) =====
    {
        mulx2(m01, BETA2); mulx2(m23, BETA2);
#pragma unroll
        for (int j = 0; j < NGRP; j++) {
            if (!UBIT(j, 5)) continue;
            unsigned bal = __ballot_sync(0xffffffffu, PBIT(j, 5) != 0u);
            unsigned mh = (bal >> shamt) & 0xffffu;
            ev_accum(mh, wb + j * (16 * 208), m01, m23);
        }
        lif_step(m01, m23, v01, v23, hl, shamt, w2b, m2, valid, po, tstride4);
    }

    // ===== tail t >= 6: encoder silent, LIF decay only =====
#pragma unroll 1
    for (int t = 6; t < T_STEPS; t++) {
        mulx2(m01, BETA2); mulx2(m23, BETA2);
        unsigned any = lif_step(m01, m23, v01, v23, hl, shamt, w2b, m2,
                                valid, po, tstride4);
        if (any == 0u) break;    // membranes <= 1, only decay: all zero ahead
    }

    // ---- spike counts (closed form; reduce within 16-lane half) ----
#pragma unroll
    for (int off = 8; off; off >>= 1)
        cnt += __shfl_xor_sync(0xffffffffu, cnt, off);
    if (valid && hl == 0)
        out[(size_t)T_STEPS * B * CDIM + b] = (float)cnt;
}

extern "C" void kernel_launch(void* const* d_in, const int* in_sizes, int n_in,
                              void* d_out, int out_size)
{
    const float* x  = (const float*)d_in[0];
    const float* W1 = (const float*)d_in[1];
    const float* W2 = (const float*)d_in[2];
    float* out = (float*)d_out;

    int B = in_sizes[0] / DDIM;
    prep_kernel<<<144, 256>>>(W1, W2, out, B);   // transpose + colsum + zero
    int blocks = (B + 15) / 16;   // 8 warps/block, 2 samples/warp
    burst_snn_kernel<<<blocks, 256>>>(x, out, B);
}

// round 15
// speedup vs baseline: 1.4286x; 1.1284x over previous
#include <cuda_runtime.h>

// BurstSnn: burst encoder + 2-layer LIF SNN, 32 timesteps.
// x [B,187] f32, W1 [50,187] f32, W2 [5,50] f32
// out: spk_rec [32,B,5] f32 then counts [B] f32
//
// Encoder = 8-entry LUT on floor(8x); spikes end by t=5. Two samples/warp.
// No smem: W1t/colsums/W2 in __device__ globals (prep kernel also zeroes
// spk_rec) -> 7 blocks/SM, one wave. Event loops process GROUP PAIRS with a
// single 32-bit mask (row addresses are linear in bit index). Bucket-sum
// reuse: V0 carries t0->t1; K5/K6 captured at t3 make t4 AND t5 loop-free.

#define T_STEPS 32
#define DDIM 187
#define HDIM 50
#define CDIM 5
#define NGRP 12
#define W1PAD 52          // floats per W1t row (208 B)
#define W2PAD 68
#define GSTR  3328        // 16 rows * 208 B = one group

// per-bucket spike-time masks, packed byte k = pattern(bucket k)
#define PAT_PACK 0x071B2B0B03050100ull

__device__ __align__(16) float g_w1t[DDIM * W1PAD + 16];  // [d][u] transposed
__device__ __align__(16) float g_col[64];                 // column sums
__device__ __align__(16) float g_w2[16 * W2PAD];          // padded W2 rows

__device__ __forceinline__ void addx2(unsigned long long &a, unsigned long long b) {
    asm("add.rn.f32x2 %0, %1, %2;" : "=l"(a) : "l"(a), "l"(b));
}
__device__ __forceinline__ void mulx2(unsigned long long &a, unsigned long long b) {
    asm("mul.rn.f32x2 %0, %1, %2;" : "=l"(a) : "l"(a), "l"(b));
}
__device__ __forceinline__ unsigned long long packx2(float lo, float hi) {
    unsigned long long r; asm("mov.b64 %0, {%1,%2};" : "=l"(r) : "f"(lo), "f"(hi)); return r;
}
__device__ __forceinline__ void unpackx2(unsigned long long v, float &lo, float &hi) {
    asm("mov.b64 {%0,%1}, %2;" : "=f"(lo), "=f"(hi) : "l"(v));
}

// -------- prep: transpose W1, colsums, pad W2, zero spk_rec --------
__global__ void prep_kernel(const float* __restrict__ W1,
                            const float* __restrict__ W2,
                            float* __restrict__ out, int B)
{
    const int tid = threadIdx.x;
    const int blk = blockIdx.x;
    if (blk < 38) {
        int idx = blk * 256 + tid;
        if (idx < DDIM * W1PAD) {
            int d = idx / W1PAD, u = idx - d * W1PAD;
            g_w1t[idx] = (u < HDIM) ? W1[u * DDIM + d] : 0.0f;
        }
    } else if (blk == 38) {
        if (tid < 64) {
            float sa = 0.0f, sb = 0.0f;
            if (tid < HDIM) {
                const float* row = W1 + tid * DDIM;
                int d = 0;
                for (; d + 1 < DDIM; d += 2) { sa += row[d]; sb += row[d + 1]; }
                for (; d < DDIM; d++) sa += row[d];
            }
            g_col[tid] = sa + sb;
        } else if (tid < 80) {
            g_w1t[DDIM * W1PAD + (tid - 64)] = 0.0f;
        }
    } else if (blk == 39) {
        for (int i = tid; i < 16 * W2PAD; i += 256) {
            int c = i / W2PAD, h = i - c * W2PAD;
            g_w2[i] = (c < CDIM && h < HDIM) ? W2[c * HDIM + h] : 0.0f;
        }
    } else {                              // blocks 40..143: zero spk_rec
        float4* o4 = (float4*)out;
        int n4 = (T_STEPS * B * CDIM) >> 2;
        int start = (blk - 40) * 256 + tid;
        for (int i = start; i < n4; i += 104 * 256)
            o4[i] = make_float4(0.f, 0.f, 0.f, 0.f);
    }
}

// pair-unrolled single-chain event accumulation; mask may span 2 groups
// (addresses are linear in bit index: gb + bit*208)
__device__ __forceinline__ void ev_accum(unsigned mh, const char* gb,
                                         unsigned long long &A01,
                                         unsigned long long &A23) {
    while (mh) {
        int i0 = __ffs(mh) - 1; mh &= mh - 1;
        const ulonglong2 w0 = *(const ulonglong2*)(gb + i0 * 208);
        if (mh) {
            int i1 = __ffs(mh) - 1; mh &= mh - 1;
            const ulonglong2 w1 = *(const ulonglong2*)(gb + i1 * 208);
            addx2(A01, w0.x); addx2(A23, w0.y);
            addx2(A01, w1.x); addx2(A23, w1.y);
        } else {
            addx2(A01, w0.x); addx2(A23, w0.y);
        }
    }
}

// layer-2 sparse gather + LIF2 + store (shared by fixed and tail steps)
__device__ __forceinline__ void l2_core(unsigned anyS1,
                                        unsigned b0, unsigned b1,
                                        unsigned b2, unsigned b3,
                                        int hl, int shamt,
                                        const float* __restrict__ w2b,
                                        float &m2, bool valid, bool &sp2,
                                        float* &po, unsigned tstride4) {
    float cur2 = 0.0f;
    if (anyS1) {
        unsigned f;
        f = (b0 >> shamt) & 0xffffu;
        while (f) { int i = __ffs(f) - 1; f &= f - 1;
                    if (hl < CDIM) cur2 += w2b[4 * i + 0]; }
        f = (b1 >> shamt) & 0xffffu;
        while (f) { int i = __ffs(f) - 1; f &= f - 1;
                    if (hl < CDIM) cur2 += w2b[4 * i + 1]; }
        f = (b2 >> shamt) & 0xffffu;
        while (f) { int i = __ffs(f) - 1; f &= f - 1;
                    if (hl < CDIM) cur2 += w2b[4 * i + 2]; }
        f = (b3 >> shamt) & 0xffffu;
        while (f) { int i = __ffs(f) - 1; f &= f - 1;
                    if (hl < CDIM) cur2 += w2b[4 * i + 3]; }
    }
    m2 = 0.9f * m2 + cur2;
    sp2 = (hl < CDIM) && (m2 > 1.0f);
    if (sp2) { m2 -= 1.0f; if (valid) *po = 1.0f; }
    po = (float*)((char*)po + tstride4);
}

// LIF1 threshold/reset + layer-2/store. Fixed steps: no quiescence ballot.
__device__ __forceinline__ void lif_fixed(unsigned long long &m01,
                                          unsigned long long &m23,
                                          bool v01, bool v23,
                                          int hl, int shamt,
                                          const float* __restrict__ w2b,
                                          float &m2, bool valid,
                                          float* &po, unsigned tstride4) {
    float a0, a1, a2, a3;
    unpackx2(m01, a0, a1); unpackx2(m23, a2, a3);
    bool s0 = v01 && (a0 > 1.0f), s1 = v01 && (a1 > 1.0f);
    bool s2 = v23 && (a2 > 1.0f), s3 = v23 && (a3 > 1.0f);
    if (s0) a0 -= 1.0f; if (s1) a1 -= 1.0f;
    if (s2) a2 -= 1.0f; if (s3) a3 -= 1.0f;
    m01 = packx2(a0, a1); m23 = packx2(a2, a3);
    unsigned b0 = __ballot_sync(0xffffffffu, s0);
    unsigned b1 = __ballot_sync(0xffffffffu, s1);
    unsigned b2 = __ballot_sync(0xffffffffu, s2);
    unsigned b3 = __ballot_sync(0xffffffffu, s3);
    bool sp2;
    l2_core(b0 | b1 | b2 | b3, b0, b1, b2, b3, hl, shamt, w2b, m2,
            valid, sp2, po, tstride4);
}

// Tail steps: also returns activity flag for the quiescence break.
__device__ __forceinline__ unsigned lif_tail(unsigned long long &m01,
                                             unsigned long long &m23,
                                             bool v01, bool v23,
                                             int hl, int shamt,
                                             const float* __restrict__ w2b,
                                             float &m2, bool valid,
                                             float* &po, unsigned tstride4) {
    float a0, a1, a2, a3;
    unpackx2(m01, a0, a1); unpackx2(m23, a2, a3);
    bool s0 = v01 && (a0 > 1.0f), s1 = v01 && (a1 > 1.0f);
    bool s2 = v23 && (a2 > 1.0f), s3 = v23 && (a3 > 1.0f);
    if (s0) a0 -= 1.0f; if (s1) a1 -= 1.0f;
    if (s2) a2 -= 1.0f; if (s3) a3 -= 1.0f;
    m01 = packx2(a0, a1); m23 = packx2(a2, a3);
    unsigned b0 = __ballot_sync(0xffffffffu, s0);
    unsigned b1 = __ballot_sync(0xffffffffu, s1);
    unsigned b2 = __ballot_sync(0xffffffffu, s2);
    unsigned b3 = __ballot_sync(0xffffffffu, s3);
    unsigned anyS1 = b0 | b1 | b2 | b3;
    bool sp2;
    l2_core(anyS1, b0, b1, b2, b3, hl, shamt, w2b, m2, valid, sp2, po, tstride4);
    unsigned anyS2 = __ballot_sync(0xffffffffu, sp2);
    return anyS1 | anyS2;
}

// packed-pattern access (j compile-time in unrolled loops)
#define PATW(j)   ((j) < 4 ? pA : ((j) < 8 ? pB : pC))
#define UNIW(j)   ((j) < 4 ? uA : ((j) < 8 ? uB : uC))
#define PBYTE(j)  ((PATW(j) >> (8 * ((j) & 3))) & 0xffu)
#define PBIT(j,t) ((PATW(j) >> (8 * ((j) & 3) + (t))) & 1u)
#define UBIT(j,t) ((UNIW(j) >> (8 * ((j) & 3) + (t))) & 1u)

// combine two per-half 16-bit masks into one 32-bit pair mask
#define PAIRMASK(bal0, bal1, hi_mask) \
    ((((bal0) >> shamt) & 0xffffu) | ((((bal1) >> shamt) & (hi_mask)) << 16))

__global__ __launch_bounds__(256, 7)
void burst_snn_kernel(const float* __restrict__ x,
                      float* __restrict__ out, int B)
{
    const int tid  = threadIdx.x;
    const int lane = tid & 31;
    const int hl   = lane & 15;
    const int half = lane >> 4;
    const int b    = (blockIdx.x * 8 + (tid >> 5)) * 2 + half;
    const bool valid = (b < B);

    const unsigned long long BETA2 = packx2(0.9f, 0.9f);

    // ---- encoder LUT: packed spike patterns, byte per group ----
    const float* xb = x + (size_t)b * DDIM;
    unsigned pA = 0u, pB = 0u, pC = 0u;
#pragma unroll
    for (int j = 0; j < NGRP; j++) {
        int d = hl + 16 * j;
        unsigned p = 0u;
        if (valid && d < DDIM) {
            unsigned bucket = (unsigned)(__ldg(xb + d) * 8.0f);   // exact
            p = (unsigned)((PAT_PACK >> (bucket * 8)) & 0xffu);
        }
        if (j < 4)      pA |= p << (8 * j);
        else if (j < 8) pB |= p << (8 * (j - 4));
        else            pC |= p << (8 * (j - 8));
    }
    int cnt = __popc(pA) + __popc(pB) + __popc(pC);

    const unsigned uA = __reduce_or_sync(0xffffffffu, pA);
    const unsigned uB = __reduce_or_sync(0xffffffffu, pB);
    const unsigned uC = __reduce_or_sync(0xffffffffu, pC);

    const bool v01 = (hl < 13), v23 = (hl < 12);

    unsigned long long m01, m23;
    float m2 = 0.0f;

    const char*  wb  = (const char*)g_w1t + hl * 16;
    const float* w2b = g_w2 + hl * W2PAD;
    const int shamt = lane & 16;
    float* po = out + b * CDIM + hl;
    const unsigned tstride4 = (unsigned)B * CDIM * sizeof(float);

    const ulonglong2 cs = *(const ulonglong2*)((const char*)g_col + hl * 16);
    float g0, g1, g2, g3;
    unpackx2(cs.x, g0, g1); unpackx2(cs.y, g2, g3);

    unsigned long long c01 = 0ull, c23 = 0ull;   // bucket-sum accumulator

    // ===== t = 0: complement (non-spikers = bucket 0) -> c = V0 =====
    {
#pragma unroll
        for (int k = 0; k < 6; k++) {
            const int j0 = 2 * k, j1 = 2 * k + 1;
            unsigned bal0 = __ballot_sync(0xffffffffu, PBIT(j0, 0) != 0u);
            unsigned bal1 = __ballot_sync(0xffffffffu, PBIT(j1, 0) != 0u);
            unsigned mh = PAIRMASK(~bal0, ~bal1, (k == 5) ? 0x07ffu : 0xffffu);
            ev_accum(mh, wb + j0 * GSTR, c01, c23);
        }
        float c0, c1, c2, c3;
        unpackx2(c01, c0, c1); unpackx2(c23, c2, c3);
        m01 = packx2(g0 - c0, g1 - c1);
        m23 = packx2(g2 - c2, g3 - c3);
        lif_fixed(m01, m23, v01, v23, hl, shamt, w2b, m2, valid, po, tstride4);
    }

    // ===== t = 1: c continues (add buckets {1,2}); cur = colsum - c =====
    {
        mulx2(m01, BETA2); mulx2(m23, BETA2);
#pragma unroll
        for (int k = 0; k < 6; k++) {
            const int j0 = 2 * k, j1 = 2 * k + 1;
            unsigned bal0 = __ballot_sync(0xffffffffu, (PBYTE(j0) & 3u) == 1u);
            unsigned bal1 = __ballot_sync(0xffffffffu, (PBYTE(j1) & 3u) == 1u);
            unsigned mh = PAIRMASK(bal0, bal1, 0xffffu);
            ev_accum(mh, wb + j0 * GSTR, c01, c23);
        }
        float a0, a1, a2, a3, c0, c1, c2, c3;
        unpackx2(m01, a0, a1); unpackx2(m23, a2, a3);
        unpackx2(c01, c0, c1); unpackx2(c23, c2, c3);
        a0 += g0 - c0; a1 += g1 - c1; a2 += g2 - c2; a3 += g3 - c3;
        m01 = packx2(a0, a1); m23 = packx2(a2, a3);
        lif_fixed(m01, m23, v01, v23, hl, shamt, w2b, m2, valid, po, tstride4);
    }

    // ===== t = 2: sparse events (buckets {2,7} = pattern bit 2) =====
    {
        mulx2(m01, BETA2); mulx2(m23, BETA2);
#pragma unroll
        for (int k = 0; k < 6; k++) {
            const int j0 = 2 * k, j1 = 2 * k + 1;
            if (!UBIT(j0, 2) && !UBIT(j1, 2)) continue;
            unsigned bal0 = __ballot_sync(0xffffffffu, PBIT(j0, 2) != 0u);
            unsigned bal1 = __ballot_sync(0xffffffffu, PBIT(j1, 2) != 0u);
            unsigned mh = PAIRMASK(bal0, bal1, 0xffffu);
            ev_accum(mh, wb + j0 * GSTR, m01, m23);
        }
        lif_fixed(m01, m23, v01, v23, hl, shamt, w2b, m2, valid, po, tstride4);
    }

    // ===== t = 3: bucket4 -> m ; bucket6 -> K6 ; bucket5 -> K5 =====
    unsigned long long k6_01 = 0ull, k6_23 = 0ull;
    unsigned long long k5_01 = 0ull, k5_23 = 0ull;
    {
        mulx2(m01, BETA2); mulx2(m23, BETA2);
#pragma unroll
        for (int k = 0; k < 6; k++) {
            const int j0 = 2 * k, j1 = 2 * k + 1;
            if (UBIT(j0, 3) || UBIT(j1, 3)) {   // any bucket in {4,5,6}
                unsigned bal0 = __ballot_sync(0xffffffffu,
                                              ((PBYTE(j0) >> 3) & 7u) == 1u);
                unsigned bal1 = __ballot_sync(0xffffffffu,
                                              ((PBYTE(j1) >> 3) & 7u) == 1u);
                unsigned mh = PAIRMASK(bal0, bal1, 0xffffu);
                ev_accum(mh, wb + j0 * GSTR, m01, m23);       // bucket 4
            }
            if (UBIT(j0, 4) || UBIT(j1, 4)) {
                unsigned bal0 = __ballot_sync(0xffffffffu, PBIT(j0, 4) != 0u);
                unsigned bal1 = __ballot_sync(0xffffffffu, PBIT(j1, 4) != 0u);
                unsigned mh = PAIRMASK(bal0, bal1, 0xffffu);
                ev_accum(mh, wb + j0 * GSTR, k6_01, k6_23);   // bucket 6
            }
            if (UBIT(j0, 5) || UBIT(j1, 5)) {
                unsigned bal0 = __ballot_sync(0xffffffffu, PBIT(j0, 5) != 0u);
                unsigned bal1 = __ballot_sync(0xffffffffu, PBIT(j1, 5) != 0u);
                unsigned mh = PAIRMASK(bal0, bal1, 0xffffu);
                ev_accum(mh, wb + j0 * GSTR, k5_01, k5_23);   // bucket 5
            }
        }
        addx2(m01, k5_01); addx2(m23, k5_23);
        addx2(m01, k6_01); addx2(m23, k6_23);
        lif_fixed(m01, m23, v01, v23, hl, shamt, w2b, m2, valid, po, tstride4);
    }

    // ===== t = 4: cur = K6 (loop-free) =====
    {
        mulx2(m01, BETA2); mulx2(m23, BETA2);
        addx2(m01, k6_01); addx2(m23, k6_23);
        lif_fixed(m01, m23, v01, v23, hl, shamt, w2b, m2, valid, po, tstride4);
    }

    // ===== t = 5: cur = K5 (loop-free) =====
    {
        mulx2(m01, BETA2); mulx2(m23, BETA2);
        addx2(m01, k5_01); addx2(m23, k5_23);
        lif_fixed(m01, m23, v01, v23, hl, shamt, w2b, m2, valid, po, tstride4);
    }

    // ===== tail t >= 6: encoder silent, LIF decay only =====
#pragma unroll 1
    for (int t = 6; t < T_STEPS; t++) {
        mulx2(m01, BETA2); mulx2(m23, BETA2);
        unsigned any = lif_tail(m01, m23, v01, v23, hl, shamt, w2b, m2,
                                valid, po, tstride4);
        if (any == 0u) break;    // membranes <= 1, only decay: all zero ahead
    }

    // ---- spike counts (closed form; reduce within 16-lane half) ----
#pragma unroll
    for (int off = 8; off; off >>= 1)
        cnt += __shfl_xor_sync(0xffffffffu, cnt, off);
    if (valid && hl == 0)
        out[(size_t)T_STEPS * B * CDIM + b] = (float)cnt;
}

extern "C" void kernel_launch(void* const* d_in, const int* in_sizes, int n_in,
                              void* d_out, int out_size)
{
    const float* x  = (const float*)d_in[0];
    const float* W1 = (const float*)d_in[1];
    const float* W2 = (const float*)d_in[2];
    float* out = (float*)d_out;

    int B = in_sizes[0] / DDIM;
    prep_kernel<<<144, 256>>>(W1, W2, out, B);   // transpose + colsum + zero
    int blocks = (B + 15) / 16;   // 8 warps/block, 2 samples/warp
    burst_snn_kernel<<<blocks, 256>>>(x, out, B);
}